// round 1
// baseline (speedup 1.0000x reference)
#include <cuda_runtime.h>
#include <math.h>

#define NQN 1000
#define NTN 100000
#define EQN 16000
#define ETN 800000
#define KVN 512
#define NMAP 200
#define D 128
#define DBIL 64
#define DMLP 192

// ---------------- scratch (device globals: no allocation allowed) ----------------
__device__ float g_Hq[NQN * D];
__device__ float g_Ht[(size_t)NTN * D];
__device__ float g_Aq[NQN * D];
__device__ float g_At[(size_t)NTN * D];
__device__ float g_dinvq[NQN];
__device__ float g_dinvt[NTN];
__device__ float g_coefq[EQN];
__device__ float g_coeft[ETN];
__device__ float g_T[DBIL * D];
__device__ float g_feat[KVN * DMLP];

// ---------------- small utility kernels ----------------
__global__ void k_zero(float* p, int n) {
    int i = blockIdx.x * blockDim.x + threadIdx.x;
    if (i < n) p[i] = 0.f;
}

__global__ void k_deg(const int* __restrict__ dst, float* deg, int E) {
    int e = blockIdx.x * blockDim.x + threadIdx.x;
    if (e < E) atomicAdd(&deg[dst[e]], 1.f);
}

__global__ void k_dinv(float* deg, int n) {
    int i = blockIdx.x * blockDim.x + threadIdx.x;
    if (i < n) deg[i] = rsqrtf(deg[i] + 1.f);
}

__global__ void k_coef(const int* __restrict__ ei, const float* __restrict__ dinv,
                       float* __restrict__ coef, int E) {
    int e = blockIdx.x * blockDim.x + threadIdx.x;
    if (e < E) coef[e] = dinv[ei[e]] * dinv[ei[E + e]];
}

// ---------------- GEMM: H[N,128] = X[N,128] @ W[128,128] ----------------
// 64 rows x 128 cols per block, 256 threads, 4x8 micro-tile per thread.
__global__ void k_gemm(const float* __restrict__ X, const float* __restrict__ W,
                       float* __restrict__ H, int N) {
    __shared__ float Xs[64][33];   // padded: conflict-free
    __shared__ float Ws[32][128];
    int t = threadIdx.x;
    int row0 = blockIdx.x * 64;
    int tx = t & 15;       // col group: cols tx + 16*j
    int ty = t >> 4;       // row group: rows ty*4 + i

    float acc[4][8];
#pragma unroll
    for (int i = 0; i < 4; i++)
#pragma unroll
        for (int j = 0; j < 8; j++) acc[i][j] = 0.f;

    for (int k0 = 0; k0 < 128; k0 += 32) {
        // load X tile 64x32
#pragma unroll
        for (int i = t; i < 64 * 32; i += 256) {
            int r = i >> 5, k = i & 31;
            int gr = row0 + r;
            Xs[r][k] = (gr < N) ? X[(size_t)gr * D + k0 + k] : 0.f;
        }
        // load W tile 32x128
#pragma unroll
        for (int i = t; i < 32 * 128; i += 256) {
            int k = i >> 7, c = i & 127;
            Ws[k][c] = W[(k0 + k) * D + c];
        }
        __syncthreads();
#pragma unroll
        for (int k = 0; k < 32; k++) {
            float a[4], b[8];
#pragma unroll
            for (int i = 0; i < 4; i++) a[i] = Xs[ty * 4 + i][k];
#pragma unroll
            for (int j = 0; j < 8; j++) b[j] = Ws[k][tx + 16 * j];
#pragma unroll
            for (int i = 0; i < 4; i++)
#pragma unroll
                for (int j = 0; j < 8; j++) acc[i][j] = fmaf(a[i], b[j], acc[i][j]);
        }
        __syncthreads();
    }
#pragma unroll
    for (int i = 0; i < 4; i++) {
        int gr = row0 + ty * 4 + i;
        if (gr < N) {
#pragma unroll
            for (int j = 0; j < 8; j++) H[(size_t)gr * D + tx + 16 * j] = acc[i][j];
        }
    }
}

// ---------------- A = dinv^2 * H + bias (self-loop + bias init) ----------------
__global__ void k_self(const float* __restrict__ H, const float* __restrict__ dinv,
                       const float* __restrict__ bias, float* __restrict__ A, int N) {
    int idx = blockIdx.x * blockDim.x + threadIdx.x;
    int row = idx >> 5, lane = idx & 31;
    if (row >= N) return;
    float s = dinv[row];
    s *= s;
    float4 h = ((const float4*)(H + (size_t)row * D))[lane];
    float4 b = ((const float4*)bias)[lane];
    float4 a;
    a.x = fmaf(h.x, s, b.x);
    a.y = fmaf(h.y, s, b.y);
    a.z = fmaf(h.z, s, b.z);
    a.w = fmaf(h.w, s, b.w);
    ((float4*)(A + (size_t)row * D))[lane] = a;
}

// ---------------- edge scatter: A[dst] += coef * H[src] ----------------
__global__ void k_scatter(const int* __restrict__ ei, const float* __restrict__ coef,
                          const float* __restrict__ H, float* __restrict__ A, int E) {
    int idx = blockIdx.x * blockDim.x + threadIdx.x;
    int e = idx >> 5;
    if (e >= E) return;
    int lane = idx & 31;
    int s = ei[e];
    int d = ei[E + e];
    float c = coef[e];
    float4 v = ((const float4*)(H + (size_t)s * D))[lane];
    v.x *= c; v.y *= c; v.z *= c; v.w *= c;
    float* ap = A + (size_t)d * D + lane * 4;
    asm volatile("red.global.add.v4.f32 [%0], {%1,%2,%3,%4};"
                 :: "l"(ap), "f"(v.x), "f"(v.y), "f"(v.z), "f"(v.w) : "memory");
}

// ---------------- row L2-normalize (+ optional ELU) ----------------
__global__ void k_norm(const float* __restrict__ A, float* __restrict__ X, int N, int elu) {
    int idx = blockIdx.x * blockDim.x + threadIdx.x;
    int row = idx >> 5, lane = idx & 31;
    if (row >= N) return;
    float4 y = ((const float4*)(A + (size_t)row * D))[lane];
    float s = y.x * y.x + y.y * y.y + y.z * y.z + y.w * y.w;
#pragma unroll
    for (int o = 16; o > 0; o >>= 1) s += __shfl_xor_sync(0xFFFFFFFFu, s, o);
    float inv = 1.f / fmaxf(sqrtf(s), 1e-12f);
    y.x *= inv; y.y *= inv; y.z *= inv; y.w *= inv;
    if (elu) {
        y.x = y.x > 0.f ? y.x : expm1f(y.x);
        y.y = y.y > 0.f ? y.y : expm1f(y.y);
        y.z = y.z > 0.f ? y.z : expm1f(y.z);
        y.w = y.w > 0.f ? y.w : expm1f(y.w);
    }
    ((float4*)(X + (size_t)row * D))[lane] = y;
}

// ---------------- consensus: Xt[v_map[i]] = Xq[u_map[i]] ----------------
__global__ void k_cons(const float* __restrict__ Xq, float* __restrict__ Xt,
                       const int* __restrict__ umap, const int* __restrict__ vmap) {
    int idx = blockIdx.x * blockDim.x + threadIdx.x;
    int row = idx >> 5, lane = idx & 31;
    if (row >= NMAP) return;
    int us = umap[row], vd = vmap[row];
    ((float4*)(Xt + (size_t)vd * D))[lane] = ((const float4*)(Xq + (size_t)us * D))[lane];
}

// ---------------- bilinear stage A: T[o,k] = sum_j a[j] * Wb[o,j,k] ----------------
__global__ void k_bilinA(const float* __restrict__ Xq, const int* __restrict__ u_ptr,
                         const float* __restrict__ Wb, float* __restrict__ T) {
    __shared__ float a[D];
    int o = blockIdx.x;      // 0..63
    int k = threadIdx.x;     // 0..127
    int u = *u_ptr;
    a[k] = Xq[(size_t)u * D + k];
    __syncthreads();
    const float* w = Wb + (size_t)o * D * D + k;
    float acc = 0.f;
#pragma unroll 8
    for (int j = 0; j < D; j++) acc = fmaf(a[j], w[(size_t)j * D], acc);
    T[o * D + k] = acc;
}

// ---------------- bilinear stage B: feat[v, col0+o] = T[o,:] . Xt[v_li[v],:] + bb[o]
__global__ void k_bilinB(const float* __restrict__ T, const float* __restrict__ Xt,
                         const int* __restrict__ v_li, const float* __restrict__ bb,
                         float* __restrict__ feat, int col0) {
    __shared__ float x[D];
    int v = blockIdx.x;      // 0..511
    int t = threadIdx.x;     // 0..63
    int vv = v_li[v];
    x[t] = Xt[(size_t)vv * D + t];
    x[t + 64] = Xt[(size_t)vv * D + 64 + t];
    __syncthreads();
    const float* tr = T + t * D;
    float acc = bb[t];
#pragma unroll 8
    for (int k = 0; k < D; k++) acc = fmaf(tr[k], x[k], acc);
    feat[v * DMLP + col0 + t] = acc;
}

// ---------------- MLP head: 192 -> 96 -> 48 -> 1 ----------------
__global__ void k_mlp(const float* __restrict__ feat,
                      const float* __restrict__ W1, const float* __restrict__ b1,
                      const float* __restrict__ W2, const float* __restrict__ b2,
                      const float* __restrict__ W3, const float* __restrict__ b3,
                      float* __restrict__ out) {
    __shared__ float f[DMLP];
    __shared__ float h1[96];
    __shared__ float h2[48];
    int v = blockIdx.x;      // 0..511
    int t = threadIdx.x;     // 0..95
    f[t] = feat[v * DMLP + t];
    f[t + 96] = feat[v * DMLP + 96 + t];
    __syncthreads();
    float acc = b1[t];
#pragma unroll 8
    for (int j = 0; j < DMLP; j++) acc = fmaf(f[j], W1[j * 96 + t], acc);
    h1[t] = fmaxf(acc, 0.f);
    __syncthreads();
    if (t < 48) {
        float a2 = b2[t];
#pragma unroll 8
        for (int j = 0; j < 96; j++) a2 = fmaf(h1[j], W2[j * 48 + t], a2);
        h2[t] = fmaxf(a2, 0.f);
    }
    __syncthreads();
    if (t == 0) {
        float s = b3[0];
#pragma unroll
        for (int j = 0; j < 48; j++) s = fmaf(h2[j], W3[j], s);
        out[v] = s;
    }
}

// ---------------- launch ----------------
extern "C" void kernel_launch(void* const* d_in, const int* in_sizes, int n_in,
                              void* d_out, int out_size) {
    const float* x_q  = (const float*)d_in[0];
    const float* x_t  = (const float*)d_in[1];
    const int*   eiq  = (const int*)d_in[2];
    const int*   eit  = (const int*)d_in[3];
    const int*   u    = (const int*)d_in[4];
    const int*   v_li = (const int*)d_in[5];
    const int*   umap = (const int*)d_in[6];
    const int*   vmap = (const int*)d_in[7];
    const float* Wg   = (const float*)d_in[8];
    const float* bg   = (const float*)d_in[9];
    const float* Wb   = (const float*)d_in[10];
    const float* bb   = (const float*)d_in[11];
    const float* W1   = (const float*)d_in[12];
    const float* b1   = (const float*)d_in[13];
    const float* W2   = (const float*)d_in[14];
    const float* b2   = (const float*)d_in[15];
    const float* W3   = (const float*)d_in[16];
    const float* b3   = (const float*)d_in[17];

    float* out = (float*)d_out;
    float* Xq  = out + KVN;              // [NQ, 128]
    float* Xt  = Xq + (size_t)NQN * D;   // [NT, 128]

    float *Hq, *Ht, *Aq, *At, *dq, *dt, *cq, *ct, *T, *feat;
    cudaGetSymbolAddress((void**)&Hq, g_Hq);
    cudaGetSymbolAddress((void**)&Ht, g_Ht);
    cudaGetSymbolAddress((void**)&Aq, g_Aq);
    cudaGetSymbolAddress((void**)&At, g_At);
    cudaGetSymbolAddress((void**)&dq, g_dinvq);
    cudaGetSymbolAddress((void**)&dt, g_dinvt);
    cudaGetSymbolAddress((void**)&cq, g_coefq);
    cudaGetSymbolAddress((void**)&ct, g_coeft);
    cudaGetSymbolAddress((void**)&T, g_T);
    cudaGetSymbolAddress((void**)&feat, g_feat);

    const int TB = 256;

    // ---- degree / normalization coefficients (graph-static, once per launch) ----
    k_zero<<<(NQN + TB - 1) / TB, TB>>>(dq, NQN);
    k_zero<<<(NTN + TB - 1) / TB, TB>>>(dt, NTN);
    k_deg<<<(EQN + TB - 1) / TB, TB>>>(eiq + EQN, dq, EQN);
    k_deg<<<(ETN + TB - 1) / TB, TB>>>(eit + ETN, dt, ETN);
    k_dinv<<<(NQN + TB - 1) / TB, TB>>>(dq, NQN);
    k_dinv<<<(NTN + TB - 1) / TB, TB>>>(dt, NTN);
    k_coef<<<(EQN + TB - 1) / TB, TB>>>(eiq, dq, cq, EQN);
    k_coef<<<(ETN + TB - 1) / TB, TB>>>(eit, dt, ct, ETN);

    for (int i = 0; i < 3; i++) {
        const float* Wi = Wg + (size_t)i * D * D;
        const float* bi = bg + (size_t)i * D;
        const float* Xq_in = (i == 0) ? x_q : Xq;
        const float* Xt_in = (i == 0) ? x_t : Xt;
        int elu = (i < 2) ? 1 : 0;

        // H = X @ W
        k_gemm<<<(NQN + 63) / 64, TB>>>(Xq_in, Wi, Hq, NQN);
        k_gemm<<<(NTN + 63) / 64, TB>>>(Xt_in, Wi, Ht, NTN);

        // A = dinv^2*H + b   (self-loop + bias)
        k_self<<<((NQN * 32) + TB - 1) / TB, TB>>>(Hq, dq, bi, Aq, NQN);
        k_self<<<((size_t)(NTN) * 32 + TB - 1) / TB, TB>>>(Ht, dt, bi, At, NTN);

        // A[dst] += coef * H[src]
        k_scatter<<<((EQN * 32) + TB - 1) / TB, TB>>>(eiq, cq, Hq, Aq, EQN);
        k_scatter<<<((size_t)(ETN) * 32 + TB - 1) / TB, TB>>>(eit, ct, Ht, At, ETN);

        // X = l2norm(A) (+elu)
        k_norm<<<((NQN * 32) + TB - 1) / TB, TB>>>(Aq, Xq, NQN, elu);
        k_norm<<<((size_t)(NTN) * 32 + TB - 1) / TB, TB>>>(At, Xt, NTN, elu);

        // consensus
        k_cons<<<(NMAP * 32 + TB - 1) / TB, TB>>>(Xq, Xt, umap, vmap);

        // bilinear -> feat[:, i*64 : (i+1)*64]
        k_bilinA<<<DBIL, D>>>(Xq, u, Wb + (size_t)i * DBIL * D * D, T);
        k_bilinB<<<KVN, DBIL>>>(T, Xt, v_li, bb + (size_t)i * DBIL, feat, i * DBIL);
    }

    // MLP head
    k_mlp<<<KVN, 96>>>(feat, W1, b1, W2, b2, W3, b3, out);
}

// round 2
// speedup vs baseline: 1.0248x; 1.0248x over previous
#include <cuda_runtime.h>
#include <math.h>

#define NQN 1000
#define NTN 100000
#define EQN 16000
#define ETN 800000
#define KVN 512
#define NMAP 200
#define D 128
#define DBIL 64
#define DMLP 192

// ---------------- scratch (device globals: no allocation allowed) ----------------
__device__ float g_Hq[NQN * D];
__device__ float g_Ht[(size_t)NTN * D];
__device__ float g_dinvq[NQN];
__device__ float g_dinvt[NTN];
__device__ int   g_cntq[NQN];
__device__ int   g_cntt[NTN];
__device__ int   g_rowq[NQN + 1];
__device__ int   g_rowt[NTN + 1];
__device__ int   g_colq[EQN];
__device__ int   g_colt[ETN];
__device__ float g_valq[EQN];
__device__ float g_valt[ETN];
__device__ float g_T[DBIL * D];
__device__ float g_feat[KVN * DMLP];

// ---------------- CSR build ----------------
__global__ void k_zeroi(int* p, int n) {
    int i = blockIdx.x * blockDim.x + threadIdx.x;
    if (i < n) p[i] = 0;
}

__global__ void k_hist(const int* __restrict__ dst, int* cnt, int E) {
    int e = blockIdx.x * blockDim.x + threadIdx.x;
    if (e < E) atomicAdd(&cnt[dst[e]], 1);
}

// single-block exclusive scan: rowptr from cnt, also dinv = rsqrt(cnt+1)
__global__ void k_scan(const int* __restrict__ cnt, int* __restrict__ rowptr,
                       float* __restrict__ dinv, int N) {
    __shared__ int ssum[1024];
    int t = threadIdx.x;
    int chunk = (N + 1023) / 1024;
    int beg = t * chunk;
    int end = beg + chunk; if (end > N) end = N;
    int s = 0;
    for (int i = beg; i < end && i >= 0; i++) s += cnt[i];
    ssum[t] = s;
    __syncthreads();
    for (int off = 1; off < 1024; off <<= 1) {
        int v = (t >= off) ? ssum[t - off] : 0;
        __syncthreads();
        ssum[t] += v;
        __syncthreads();
    }
    int run = (t == 0) ? 0 : ssum[t - 1];
    for (int i = beg; i < end && i >= 0; i++) {
        rowptr[i] = run;
        int c = cnt[i];
        dinv[i] = rsqrtf((float)c + 1.f);
        run += c;
    }
    if (beg < N && end == N) rowptr[N] = run;
}

__global__ void k_fill(const int* __restrict__ ei, const int* __restrict__ rowptr,
                       int* cursor, int* col, int E) {
    int e = blockIdx.x * blockDim.x + threadIdx.x;
    if (e >= E) return;
    int s = ei[e];
    int d = ei[E + e];
    int pos = rowptr[d] + atomicAdd(&cursor[d], 1);
    col[pos] = s;
}

// per-row sort by src (canonical, deterministic) + compute coef values
__global__ void k_rowfin(const int* __restrict__ rowptr, int* __restrict__ col,
                         float* __restrict__ val, const float* __restrict__ dinv, int N) {
    int r = blockIdx.x * blockDim.x + threadIdx.x;
    if (r >= N) return;
    int b = rowptr[r], e = rowptr[r + 1];
    for (int i = b + 1; i < e; i++) {
        int key = col[i];
        int j = i - 1;
        while (j >= b && col[j] > key) { col[j + 1] = col[j]; j--; }
        col[j + 1] = key;
    }
    float dr = dinv[r];
    for (int i = b; i < e; i++) val[i] = dinv[col[i]] * dr;
}

// ---------------- GEMM: H[N,128] = X[N,128] @ W[128,128] ----------------
__global__ void k_gemm(const float* __restrict__ X, const float* __restrict__ W,
                       float* __restrict__ H, int N) {
    __shared__ float Xs[64][33];
    __shared__ float Ws[32][128];
    int t = threadIdx.x;
    int row0 = blockIdx.x * 64;
    int tx = t & 15;
    int ty = t >> 4;

    float acc[4][8];
#pragma unroll
    for (int i = 0; i < 4; i++)
#pragma unroll
        for (int j = 0; j < 8; j++) acc[i][j] = 0.f;

    for (int k0 = 0; k0 < 128; k0 += 32) {
#pragma unroll
        for (int i = t; i < 64 * 32; i += 256) {
            int r = i >> 5, k = i & 31;
            int gr = row0 + r;
            Xs[r][k] = (gr < N) ? X[(size_t)gr * D + k0 + k] : 0.f;
        }
#pragma unroll
        for (int i = t; i < 32 * 128; i += 256) {
            int k = i >> 7, c = i & 127;
            Ws[k][c] = W[(k0 + k) * D + c];
        }
        __syncthreads();
#pragma unroll
        for (int k = 0; k < 32; k++) {
            float a[4], b[8];
#pragma unroll
            for (int i = 0; i < 4; i++) a[i] = Xs[ty * 4 + i][k];
#pragma unroll
            for (int j = 0; j < 8; j++) b[j] = Ws[k][tx + 16 * j];
#pragma unroll
            for (int i = 0; i < 4; i++)
#pragma unroll
                for (int j = 0; j < 8; j++) acc[i][j] = fmaf(a[i], b[j], acc[i][j]);
        }
        __syncthreads();
    }
#pragma unroll
    for (int i = 0; i < 4; i++) {
        int gr = row0 + ty * 4 + i;
        if (gr < N) {
#pragma unroll
            for (int j = 0; j < 8; j++) H[(size_t)gr * D + tx + 16 * j] = acc[i][j];
        }
    }
}

// ---------------- fused aggregation + self-loop + bias + l2norm (+elu) ----------------
// warp per destination row; CSR pull; no atomics.
__global__ void k_agg(const float* __restrict__ H, const int* __restrict__ rowptr,
                      const int* __restrict__ col, const float* __restrict__ val,
                      const float* __restrict__ dinv, const float* __restrict__ bias,
                      float* __restrict__ X, int N, int elu) {
    int idx = blockIdx.x * blockDim.x + threadIdx.x;
    int row = idx >> 5;
    if (row >= N) return;
    int lane = idx & 31;

    float s = dinv[row]; s *= s;
    float4 h = __ldg(&((const float4*)(H + (size_t)row * D))[lane]);
    float4 b = __ldg(&((const float4*)bias)[lane]);
    float ax = fmaf(h.x, s, b.x);
    float ay = fmaf(h.y, s, b.y);
    float az = fmaf(h.z, s, b.z);
    float aw = fmaf(h.w, s, b.w);

    int beg = rowptr[row], end = rowptr[row + 1];
    int j = beg;
    for (; j + 2 <= end; j += 2) {
        int s0 = col[j], s1 = col[j + 1];
        float c0 = val[j], c1 = val[j + 1];
        float4 v0 = __ldg(&((const float4*)(H + (size_t)s0 * D))[lane]);
        float4 v1 = __ldg(&((const float4*)(H + (size_t)s1 * D))[lane]);
        ax = fmaf(c0, v0.x, ax); ay = fmaf(c0, v0.y, ay);
        az = fmaf(c0, v0.z, az); aw = fmaf(c0, v0.w, aw);
        ax = fmaf(c1, v1.x, ax); ay = fmaf(c1, v1.y, ay);
        az = fmaf(c1, v1.z, az); aw = fmaf(c1, v1.w, aw);
    }
    if (j < end) {
        int s0 = col[j];
        float c0 = val[j];
        float4 v0 = __ldg(&((const float4*)(H + (size_t)s0 * D))[lane]);
        ax = fmaf(c0, v0.x, ax); ay = fmaf(c0, v0.y, ay);
        az = fmaf(c0, v0.z, az); aw = fmaf(c0, v0.w, aw);
    }

    float ss = ax * ax + ay * ay + az * az + aw * aw;
#pragma unroll
    for (int o = 16; o > 0; o >>= 1) ss += __shfl_xor_sync(0xFFFFFFFFu, ss, o);
    float inv = 1.f / fmaxf(sqrtf(ss), 1e-12f);
    ax *= inv; ay *= inv; az *= inv; aw *= inv;
    if (elu) {
        ax = ax > 0.f ? ax : expm1f(ax);
        ay = ay > 0.f ? ay : expm1f(ay);
        az = az > 0.f ? az : expm1f(az);
        aw = aw > 0.f ? aw : expm1f(aw);
    }
    float4 o4 = make_float4(ax, ay, az, aw);
    ((float4*)(X + (size_t)row * D))[lane] = o4;
}

// ---------------- consensus: Xt[v_map[i]] = Xq[u_map[i]] ----------------
__global__ void k_cons(const float* __restrict__ Xq, float* __restrict__ Xt,
                       const int* __restrict__ umap, const int* __restrict__ vmap) {
    int idx = blockIdx.x * blockDim.x + threadIdx.x;
    int row = idx >> 5, lane = idx & 31;
    if (row >= NMAP) return;
    int us = umap[row], vd = vmap[row];
    ((float4*)(Xt + (size_t)vd * D))[lane] = ((const float4*)(Xq + (size_t)us * D))[lane];
}

// ---------------- bilinear stage A: T[o,k] = sum_j a[j] * Wb[o,j,k] ----------------
__global__ void k_bilinA(const float* __restrict__ Xq, const int* __restrict__ u_ptr,
                         const float* __restrict__ Wb, float* __restrict__ T) {
    __shared__ float a[D];
    int o = blockIdx.x;
    int k = threadIdx.x;
    int u = *u_ptr;
    a[k] = Xq[(size_t)u * D + k];
    __syncthreads();
    const float* w = Wb + (size_t)o * D * D + k;
    float acc = 0.f;
#pragma unroll 8
    for (int j = 0; j < D; j++) acc = fmaf(a[j], w[(size_t)j * D], acc);
    T[o * D + k] = acc;
}

// ---------------- bilinear stage B ----------------
__global__ void k_bilinB(const float* __restrict__ T, const float* __restrict__ Xt,
                         const int* __restrict__ v_li, const float* __restrict__ bb,
                         float* __restrict__ feat, int col0) {
    __shared__ float x[D];
    int v = blockIdx.x;
    int t = threadIdx.x;
    int vv = v_li[v];
    x[t] = Xt[(size_t)vv * D + t];
    x[t + 64] = Xt[(size_t)vv * D + 64 + t];
    __syncthreads();
    const float* tr = T + t * D;
    float acc = bb[t];
#pragma unroll 8
    for (int k = 0; k < D; k++) acc = fmaf(tr[k], x[k], acc);
    feat[v * DMLP + col0 + t] = acc;
}

// ---------------- MLP head: 192 -> 96 -> 48 -> 1 ----------------
__global__ void k_mlp(const float* __restrict__ feat,
                      const float* __restrict__ W1, const float* __restrict__ b1,
                      const float* __restrict__ W2, const float* __restrict__ b2,
                      const float* __restrict__ W3, const float* __restrict__ b3,
                      float* __restrict__ out) {
    __shared__ float f[DMLP];
    __shared__ float h1[96];
    __shared__ float h2[48];
    int v = blockIdx.x;
    int t = threadIdx.x;
    f[t] = feat[v * DMLP + t];
    f[t + 96] = feat[v * DMLP + 96 + t];
    __syncthreads();
    float acc = b1[t];
#pragma unroll 8
    for (int j = 0; j < DMLP; j++) acc = fmaf(f[j], W1[j * 96 + t], acc);
    h1[t] = fmaxf(acc, 0.f);
    __syncthreads();
    if (t < 48) {
        float a2 = b2[t];
#pragma unroll 8
        for (int j = 0; j < 96; j++) a2 = fmaf(h1[j], W2[j * 48 + t], a2);
        h2[t] = fmaxf(a2, 0.f);
    }
    __syncthreads();
    if (t == 0) {
        float s = b3[0];
#pragma unroll
        for (int j = 0; j < 48; j++) s = fmaf(h2[j], W3[j], s);
        out[v] = s;
    }
}

// ---------------- launch ----------------
extern "C" void kernel_launch(void* const* d_in, const int* in_sizes, int n_in,
                              void* d_out, int out_size) {
    const float* x_q  = (const float*)d_in[0];
    const float* x_t  = (const float*)d_in[1];
    const int*   eiq  = (const int*)d_in[2];
    const int*   eit  = (const int*)d_in[3];
    const int*   u    = (const int*)d_in[4];
    const int*   v_li = (const int*)d_in[5];
    const int*   umap = (const int*)d_in[6];
    const int*   vmap = (const int*)d_in[7];
    const float* Wg   = (const float*)d_in[8];
    const float* bg   = (const float*)d_in[9];
    const float* Wb   = (const float*)d_in[10];
    const float* bb   = (const float*)d_in[11];
    const float* W1   = (const float*)d_in[12];
    const float* b1   = (const float*)d_in[13];
    const float* W2   = (const float*)d_in[14];
    const float* b2   = (const float*)d_in[15];
    const float* W3   = (const float*)d_in[16];
    const float* b3   = (const float*)d_in[17];

    float* out = (float*)d_out;
    float* Xq  = out + KVN;
    float* Xt  = Xq + (size_t)NQN * D;

    float *Hq, *Ht, *dq, *dt, *vq, *vt, *T, *feat;
    int *cq, *ct, *rq, *rt, *colq, *colt;
    cudaGetSymbolAddress((void**)&Hq, g_Hq);
    cudaGetSymbolAddress((void**)&Ht, g_Ht);
    cudaGetSymbolAddress((void**)&dq, g_dinvq);
    cudaGetSymbolAddress((void**)&dt, g_dinvt);
    cudaGetSymbolAddress((void**)&cq, g_cntq);
    cudaGetSymbolAddress((void**)&ct, g_cntt);
    cudaGetSymbolAddress((void**)&rq, g_rowq);
    cudaGetSymbolAddress((void**)&rt, g_rowt);
    cudaGetSymbolAddress((void**)&colq, g_colq);
    cudaGetSymbolAddress((void**)&colt, g_colt);
    cudaGetSymbolAddress((void**)&vq, g_valq);
    cudaGetSymbolAddress((void**)&vt, g_valt);
    cudaGetSymbolAddress((void**)&T, g_T);
    cudaGetSymbolAddress((void**)&feat, g_feat);

    const int TB = 256;

    // ---- CSR build (graph-static, once per launch) ----
    k_zeroi<<<(NQN + TB - 1) / TB, TB>>>(cq, NQN);
    k_zeroi<<<(NTN + TB - 1) / TB, TB>>>(ct, NTN);
    k_hist<<<(EQN + TB - 1) / TB, TB>>>(eiq + EQN, cq, EQN);
    k_hist<<<(ETN + TB - 1) / TB, TB>>>(eit + ETN, ct, ETN);
    k_scan<<<1, 1024>>>(cq, rq, dq, NQN);
    k_scan<<<1, 1024>>>(ct, rt, dt, NTN);
    k_zeroi<<<(NQN + TB - 1) / TB, TB>>>(cq, NQN);
    k_zeroi<<<(NTN + TB - 1) / TB, TB>>>(ct, NTN);
    k_fill<<<(EQN + TB - 1) / TB, TB>>>(eiq, rq, cq, colq, EQN);
    k_fill<<<(ETN + TB - 1) / TB, TB>>>(eit, rt, ct, colt, ETN);
    k_rowfin<<<(NQN + TB - 1) / TB, TB>>>(rq, colq, vq, dq, NQN);
    k_rowfin<<<(NTN + TB - 1) / TB, TB>>>(rt, colt, vt, dt, NTN);

    for (int i = 0; i < 3; i++) {
        const float* Wi = Wg + (size_t)i * D * D;
        const float* bi = bg + (size_t)i * D;
        const float* Xq_in = (i == 0) ? x_q : Xq;
        const float* Xt_in = (i == 0) ? x_t : Xt;
        int elu = (i < 2) ? 1 : 0;

        k_gemm<<<(NQN + 63) / 64, TB>>>(Xq_in, Wi, Hq, NQN);
        k_gemm<<<(NTN + 63) / 64, TB>>>(Xt_in, Wi, Ht, NTN);

        k_agg<<<((NQN * 32) + TB - 1) / TB, TB>>>(Hq, rq, colq, vq, dq, bi, Xq, NQN, elu);
        k_agg<<<((size_t)(NTN) * 32 + TB - 1) / TB, TB>>>(Ht, rt, colt, vt, dt, bi, Xt, NTN, elu);

        k_cons<<<(NMAP * 32 + TB - 1) / TB, TB>>>(Xq, Xt, umap, vmap);

        k_bilinA<<<DBIL, D>>>(Xq, u, Wb + (size_t)i * DBIL * D * D, T);
        k_bilinB<<<KVN, DBIL>>>(T, Xt, v_li, bb + (size_t)i * DBIL, feat, i * DBIL);
    }

    k_mlp<<<KVN, 96>>>(feat, W1, b1, W2, b2, W3, b3, out);
}

// round 3
// speedup vs baseline: 1.0285x; 1.0036x over previous
#include <cuda_runtime.h>
#include <math.h>

#define NQN 1000
#define NTN 100000
#define EQN 16000
#define ETN 800000
#define KVN 512
#define NMAP 200
#define D 128
#define DBIL 64
#define DMLP 192

// ---------------- scratch (device globals: no allocation allowed) ----------------
__device__ float g_Hq[NQN * D];
__device__ float g_Ht[(size_t)NTN * D];
__device__ float g_dinvq[NQN];
__device__ float g_dinvt[NTN];
__device__ int   g_cntq[NQN];
__device__ int   g_cntt[NTN];
__device__ int   g_rowq[NQN + 1];
__device__ int   g_rowt[NTN + 1];
__device__ int   g_colq[EQN];
__device__ int   g_colt[ETN];
__device__ float g_valq[EQN];
__device__ float g_valt[ETN];
__device__ float g_T[DBIL * D];
__device__ float g_feat[KVN * DMLP];

// ---------------- CSR build ----------------
__global__ void k_zeroi(int* p, int n) {
    int i = blockIdx.x * blockDim.x + threadIdx.x;
    if (i < n) p[i] = 0;
}

__global__ void k_hist(const int* __restrict__ dst, int* cnt, int E) {
    int e = blockIdx.x * blockDim.x + threadIdx.x;
    if (e < E) atomicAdd(&cnt[dst[e]], 1);
}

// single-block exclusive scan: rowptr from cnt, also dinv = rsqrt(cnt+1)
__global__ void k_scan(const int* __restrict__ cnt, int* __restrict__ rowptr,
                       float* __restrict__ dinv, int N) {
    __shared__ int ssum[1024];
    int t = threadIdx.x;
    int chunk = (N + 1023) / 1024;
    int beg = t * chunk;
    int end = beg + chunk; if (end > N) end = N;
    int s = 0;
    for (int i = beg; i < end && i >= 0; i++) s += cnt[i];
    ssum[t] = s;
    __syncthreads();
    for (int off = 1; off < 1024; off <<= 1) {
        int v = (t >= off) ? ssum[t - off] : 0;
        __syncthreads();
        ssum[t] += v;
        __syncthreads();
    }
    int run = (t == 0) ? 0 : ssum[t - 1];
    for (int i = beg; i < end && i >= 0; i++) {
        rowptr[i] = run;
        int c = cnt[i];
        dinv[i] = rsqrtf((float)c + 1.f);
        run += c;
    }
    if (beg < N && end == N) rowptr[N] = run;
}

__global__ void k_fill(const int* __restrict__ ei, const int* __restrict__ rowptr,
                       int* cursor, int* col, int E) {
    int e = blockIdx.x * blockDim.x + threadIdx.x;
    if (e >= E) return;
    int s = ei[e];
    int d = ei[E + e];
    int pos = rowptr[d] + atomicAdd(&cursor[d], 1);
    col[pos] = s;
}

// per-row sort by src (canonical, deterministic) + compute coef values
__global__ void k_rowfin(const int* __restrict__ rowptr, int* __restrict__ col,
                         float* __restrict__ val, const float* __restrict__ dinv, int N) {
    int r = blockIdx.x * blockDim.x + threadIdx.x;
    if (r >= N) return;
    int b = rowptr[r], e = rowptr[r + 1];
    for (int i = b + 1; i < e; i++) {
        int key = col[i];
        int j = i - 1;
        while (j >= b && col[j] > key) { col[j + 1] = col[j]; j--; }
        col[j + 1] = key;
    }
    float dr = dinv[r];
    for (int i = b; i < e; i++) val[i] = dinv[col[i]] * dr;
}

// ---------------- GEMM: H[N,128] = X[N,128] @ W[128,128] ----------------
__global__ void k_gemm(const float* __restrict__ X, const float* __restrict__ W,
                       float* __restrict__ H, int N) {
    __shared__ float Xs[64][33];
    __shared__ float Ws[32][128];
    int t = threadIdx.x;
    int row0 = blockIdx.x * 64;
    int tx = t & 15;
    int ty = t >> 4;

    float acc[4][8];
#pragma unroll
    for (int i = 0; i < 4; i++)
#pragma unroll
        for (int j = 0; j < 8; j++) acc[i][j] = 0.f;

    for (int k0 = 0; k0 < 128; k0 += 32) {
#pragma unroll
        for (int i = t; i < 64 * 32; i += 256) {
            int r = i >> 5, k = i & 31;
            int gr = row0 + r;
            Xs[r][k] = (gr < N) ? X[(size_t)gr * D + k0 + k] : 0.f;
        }
#pragma unroll
        for (int i = t; i < 32 * 128; i += 256) {
            int k = i >> 7, c = i & 127;
            Ws[k][c] = W[(k0 + k) * D + c];
        }
        __syncthreads();
#pragma unroll
        for (int k = 0; k < 32; k++) {
            float a[4], b[8];
#pragma unroll
            for (int i = 0; i < 4; i++) a[i] = Xs[ty * 4 + i][k];
#pragma unroll
            for (int j = 0; j < 8; j++) b[j] = Ws[k][tx + 16 * j];
#pragma unroll
            for (int i = 0; i < 4; i++)
#pragma unroll
                for (int j = 0; j < 8; j++) acc[i][j] = fmaf(a[i], b[j], acc[i][j]);
        }
        __syncthreads();
    }
#pragma unroll
    for (int i = 0; i < 4; i++) {
        int gr = row0 + ty * 4 + i;
        if (gr < N) {
#pragma unroll
            for (int j = 0; j < 8; j++) H[(size_t)gr * D + tx + 16 * j] = acc[i][j];
        }
    }
}

// ---------------- fused aggregation + self-loop + bias + l2norm (+elu) ----------------
// warp per destination row; CSR pull; no atomics.
__global__ void k_agg(const float* __restrict__ H, const int* __restrict__ rowptr,
                      const int* __restrict__ col, const float* __restrict__ val,
                      const float* __restrict__ dinv, const float* __restrict__ bias,
                      float* __restrict__ X, int N, int elu) {
    int idx = blockIdx.x * blockDim.x + threadIdx.x;
    int row = idx >> 5;
    if (row >= N) return;
    int lane = idx & 31;

    float s = dinv[row]; s *= s;
    float4 h = __ldg(&((const float4*)(H + (size_t)row * D))[lane]);
    float4 b = __ldg(&((const float4*)bias)[lane]);
    float ax = fmaf(h.x, s, b.x);
    float ay = fmaf(h.y, s, b.y);
    float az = fmaf(h.z, s, b.z);
    float aw = fmaf(h.w, s, b.w);

    int beg = rowptr[row], end = rowptr[row + 1];
    int j = beg;
    for (; j + 2 <= end; j += 2) {
        int s0 = col[j], s1 = col[j + 1];
        float c0 = val[j], c1 = val[j + 1];
        float4 v0 = __ldg(&((const float4*)(H + (size_t)s0 * D))[lane]);
        float4 v1 = __ldg(&((const float4*)(H + (size_t)s1 * D))[lane]);
        ax = fmaf(c0, v0.x, ax); ay = fmaf(c0, v0.y, ay);
        az = fmaf(c0, v0.z, az); aw = fmaf(c0, v0.w, aw);
        ax = fmaf(c1, v1.x, ax); ay = fmaf(c1, v1.y, ay);
        az = fmaf(c1, v1.z, az); aw = fmaf(c1, v1.w, aw);
    }
    if (j < end) {
        int s0 = col[j];
        float c0 = val[j];
        float4 v0 = __ldg(&((const float4*)(H + (size_t)s0 * D))[lane]);
        ax = fmaf(c0, v0.x, ax); ay = fmaf(c0, v0.y, ay);
        az = fmaf(c0, v0.z, az); aw = fmaf(c0, v0.w, aw);
    }

    float ss = ax * ax + ay * ay + az * az + aw * aw;
#pragma unroll
    for (int o = 16; o > 0; o >>= 1) ss += __shfl_xor_sync(0xFFFFFFFFu, ss, o);
    float inv = 1.f / fmaxf(sqrtf(ss), 1e-12f);
    ax *= inv; ay *= inv; az *= inv; aw *= inv;
    if (elu) {
        ax = ax > 0.f ? ax : expm1f(ax);
        ay = ay > 0.f ? ay : expm1f(ay);
        az = az > 0.f ? az : expm1f(az);
        aw = aw > 0.f ? aw : expm1f(aw);
    }
    float4 o4 = make_float4(ax, ay, az, aw);
    ((float4*)(X + (size_t)row * D))[lane] = o4;
}

// ---------------- consensus: Xt[v_map[i]] = Xq[u_map[i]] ----------------
__global__ void k_cons(const float* __restrict__ Xq, float* __restrict__ Xt,
                       const int* __restrict__ umap, const int* __restrict__ vmap) {
    int idx = blockIdx.x * blockDim.x + threadIdx.x;
    int row = idx >> 5, lane = idx & 31;
    if (row >= NMAP) return;
    int us = umap[row], vd = vmap[row];
    ((float4*)(Xt + (size_t)vd * D))[lane] = ((const float4*)(Xq + (size_t)us * D))[lane];
}

// ---------------- bilinear stage A: T[o,k] = sum_j a[j] * Wb[o,j,k] ----------------
__global__ void k_bilinA(const float* __restrict__ Xq, const int* __restrict__ u_ptr,
                         const float* __restrict__ Wb, float* __restrict__ T) {
    __shared__ float a[D];
    int o = blockIdx.x;
    int k = threadIdx.x;
    int u = *u_ptr;
    a[k] = Xq[(size_t)u * D + k];
    __syncthreads();
    const float* w = Wb + (size_t)o * D * D + k;
    float acc = 0.f;
#pragma unroll 8
    for (int j = 0; j < D; j++) acc = fmaf(a[j], w[(size_t)j * D], acc);
    T[o * D + k] = acc;
}

// ---------------- bilinear stage B ----------------
__global__ void k_bilinB(const float* __restrict__ T, const float* __restrict__ Xt,
                         const int* __restrict__ v_li, const float* __restrict__ bb,
                         float* __restrict__ feat, int col0) {
    __shared__ float x[D];
    int v = blockIdx.x;
    int t = threadIdx.x;
    int vv = v_li[v];
    x[t] = Xt[(size_t)vv * D + t];
    x[t + 64] = Xt[(size_t)vv * D + 64 + t];
    __syncthreads();
    const float* tr = T + t * D;
    float acc = bb[t];
#pragma unroll 8
    for (int k = 0; k < D; k++) acc = fmaf(tr[k], x[k], acc);
    feat[v * DMLP + col0 + t] = acc;
}

// ---------------- MLP head: 192 -> 96 -> 48 -> 1 ----------------
__global__ void k_mlp(const float* __restrict__ feat,
                      const float* __restrict__ W1, const float* __restrict__ b1,
                      const float* __restrict__ W2, const float* __restrict__ b2,
                      const float* __restrict__ W3, const float* __restrict__ b3,
                      float* __restrict__ out) {
    __shared__ float f[DMLP];
    __shared__ float h1[96];
    __shared__ float h2[48];
    int v = blockIdx.x;
    int t = threadIdx.x;
    f[t] = feat[v * DMLP + t];
    f[t + 96] = feat[v * DMLP + 96 + t];
    __syncthreads();
    float acc = b1[t];
#pragma unroll 8
    for (int j = 0; j < DMLP; j++) acc = fmaf(f[j], W1[j * 96 + t], acc);
    h1[t] = fmaxf(acc, 0.f);
    __syncthreads();
    if (t < 48) {
        float a2 = b2[t];
#pragma unroll 8
        for (int j = 0; j < 96; j++) a2 = fmaf(h1[j], W2[j * 48 + t], a2);
        h2[t] = fmaxf(a2, 0.f);
    }
    __syncthreads();
    if (t == 0) {
        float s = b3[0];
#pragma unroll
        for (int j = 0; j < 48; j++) s = fmaf(h2[j], W3[j], s);
        out[v] = s;
    }
}

// ---------------- launch ----------------
extern "C" void kernel_launch(void* const* d_in, const int* in_sizes, int n_in,
                              void* d_out, int out_size) {
    const float* x_q  = (const float*)d_in[0];
    const float* x_t  = (const float*)d_in[1];
    const int*   eiq  = (const int*)d_in[2];
    const int*   eit  = (const int*)d_in[3];
    const int*   u    = (const int*)d_in[4];
    const int*   v_li = (const int*)d_in[5];
    const int*   umap = (const int*)d_in[6];
    const int*   vmap = (const int*)d_in[7];
    const float* Wg   = (const float*)d_in[8];
    const float* bg   = (const float*)d_in[9];
    const float* Wb   = (const float*)d_in[10];
    const float* bb   = (const float*)d_in[11];
    const float* W1   = (const float*)d_in[12];
    const float* b1   = (const float*)d_in[13];
    const float* W2   = (const float*)d_in[14];
    const float* b2   = (const float*)d_in[15];
    const float* W3   = (const float*)d_in[16];
    const float* b3   = (const float*)d_in[17];

    float* out = (float*)d_out;
    float* Xq  = out + KVN;
    float* Xt  = Xq + (size_t)NQN * D;

    float *Hq, *Ht, *dq, *dt, *vq, *vt, *T, *feat;
    int *cq, *ct, *rq, *rt, *colq, *colt;
    cudaGetSymbolAddress((void**)&Hq, g_Hq);
    cudaGetSymbolAddress((void**)&Ht, g_Ht);
    cudaGetSymbolAddress((void**)&dq, g_dinvq);
    cudaGetSymbolAddress((void**)&dt, g_dinvt);
    cudaGetSymbolAddress((void**)&cq, g_cntq);
    cudaGetSymbolAddress((void**)&ct, g_cntt);
    cudaGetSymbolAddress((void**)&rq, g_rowq);
    cudaGetSymbolAddress((void**)&rt, g_rowt);
    cudaGetSymbolAddress((void**)&colq, g_colq);
    cudaGetSymbolAddress((void**)&colt, g_colt);
    cudaGetSymbolAddress((void**)&vq, g_valq);
    cudaGetSymbolAddress((void**)&vt, g_valt);
    cudaGetSymbolAddress((void**)&T, g_T);
    cudaGetSymbolAddress((void**)&feat, g_feat);

    const int TB = 256;

    // ---- CSR build (graph-static, once per launch) ----
    k_zeroi<<<(NQN + TB - 1) / TB, TB>>>(cq, NQN);
    k_zeroi<<<(NTN + TB - 1) / TB, TB>>>(ct, NTN);
    k_hist<<<(EQN + TB - 1) / TB, TB>>>(eiq + EQN, cq, EQN);
    k_hist<<<(ETN + TB - 1) / TB, TB>>>(eit + ETN, ct, ETN);
    k_scan<<<1, 1024>>>(cq, rq, dq, NQN);
    k_scan<<<1, 1024>>>(ct, rt, dt, NTN);
    k_zeroi<<<(NQN + TB - 1) / TB, TB>>>(cq, NQN);
    k_zeroi<<<(NTN + TB - 1) / TB, TB>>>(ct, NTN);
    k_fill<<<(EQN + TB - 1) / TB, TB>>>(eiq, rq, cq, colq, EQN);
    k_fill<<<(ETN + TB - 1) / TB, TB>>>(eit, rt, ct, colt, ETN);
    k_rowfin<<<(NQN + TB - 1) / TB, TB>>>(rq, colq, vq, dq, NQN);
    k_rowfin<<<(NTN + TB - 1) / TB, TB>>>(rt, colt, vt, dt, NTN);

    for (int i = 0; i < 3; i++) {
        const float* Wi = Wg + (size_t)i * D * D;
        const float* bi = bg + (size_t)i * D;
        const float* Xq_in = (i == 0) ? x_q : Xq;
        const float* Xt_in = (i == 0) ? x_t : Xt;
        int elu = (i < 2) ? 1 : 0;

        k_gemm<<<(NQN + 63) / 64, TB>>>(Xq_in, Wi, Hq, NQN);
        k_gemm<<<(NTN + 63) / 64, TB>>>(Xt_in, Wi, Ht, NTN);

        k_agg<<<((NQN * 32) + TB - 1) / TB, TB>>>(Hq, rq, colq, vq, dq, bi, Xq, NQN, elu);
        k_agg<<<((size_t)(NTN) * 32 + TB - 1) / TB, TB>>>(Ht, rt, colt, vt, dt, bi, Xt, NTN, elu);

        k_cons<<<(NMAP * 32 + TB - 1) / TB, TB>>>(Xq, Xt, umap, vmap);

        k_bilinA<<<DBIL, D>>>(Xq, u, Wb + (size_t)i * DBIL * D * D, T);
        k_bilinB<<<KVN, DBIL>>>(T, Xt, v_li, bb + (size_t)i * DBIL, feat, i * DBIL);
    }

    k_mlp<<<KVN, 96>>>(feat, W1, b1, W2, b2, W3, b3, out);
}

// round 6
// speedup vs baseline: 1.1926x; 1.1596x over previous
#include <cuda_runtime.h>
#include <math.h>
#include <stdint.h>

#define NQN 1000
#define NTN 100000
#define EQN 16000
#define ETN 800000
#define KVN 512
#define NMAP 200
#define D 128
#define DBIL 64
#define DMLP 192

// ---------------- scratch (device globals: no allocation allowed) ----------------
__device__ float g_Hq[NQN * D];
__device__ float g_Ht[(size_t)NTN * D];
__device__ float g_dinvq[NQN];
__device__ float g_dinvt[NTN];
__device__ int   g_cntq[NQN];
__device__ int   g_cntt[NTN];
__device__ int   g_rowq[NQN + 1];
__device__ int   g_rowt[NTN + 1];
__device__ int   g_colq[EQN];
__device__ int   g_colt[ETN];
__device__ float g_valq[EQN];
__device__ float g_valt[ETN];
__device__ int   g_partq[512];
__device__ int   g_partt[512];
__device__ float g_T[DBIL * D];
__device__ float g_feat[KVN * DMLP];

// ---------------- CSR build ----------------
__global__ void k_zeroi(int* p, int n) {
    int i = blockIdx.x * blockDim.x + threadIdx.x;
    if (i < n) p[i] = 0;
}

__global__ void k_hist(const int* __restrict__ dst, int* cnt, int E) {
    int e = blockIdx.x * blockDim.x + threadIdx.x;
    if (e < E) atomicAdd(&cnt[dst[e]], 1);
}

// per-block partial sums of cnt (256 elems/block)
__global__ void k_partial(const int* __restrict__ cnt, int* __restrict__ part, int N) {
    int t = threadIdx.x;
    int i = blockIdx.x * 256 + t;
    int c = (i < N) ? cnt[i] : 0;
    int lane = t & 31, w = t >> 5;
#pragma unroll
    for (int o = 16; o > 0; o >>= 1) c += __shfl_xor_sync(0xFFFFFFFFu, c, o);
    __shared__ int s[8];
    if (lane == 0) s[w] = c;
    __syncthreads();
    if (t == 0) {
        int sum = 0;
#pragma unroll
        for (int j = 0; j < 8; j++) sum += s[j];
        part[blockIdx.x] = sum;
    }
}

// single block: exclusive scan of <=512 partials
__global__ void k_scanp(int* part, int nb) {
    __shared__ int s[512];
    int t = threadIdx.x;
    int v = (t < nb) ? part[t] : 0;
    s[t] = v;
    __syncthreads();
    for (int o = 1; o < 512; o <<= 1) {
        int u = (t >= o) ? s[t - o] : 0;
        __syncthreads();
        s[t] += u;
        __syncthreads();
    }
    if (t < nb) part[t] = s[t] - v;   // exclusive
}

// block-local exclusive scan + global offset -> rowptr, dinv
__global__ void k_rowptr(const int* __restrict__ cnt, const int* __restrict__ poff,
                         int* __restrict__ rowptr, float* __restrict__ dinv, int N) {
    int t = threadIdx.x;
    int i = blockIdx.x * 256 + t;
    int c = (i < N) ? cnt[i] : 0;
    int lane = t & 31, w = t >> 5;
    int v = c;
#pragma unroll
    for (int o = 1; o < 32; o <<= 1) {
        int u = __shfl_up_sync(0xFFFFFFFFu, v, o);
        if (lane >= o) v += u;
    }
    __shared__ int ws[8];
    if (lane == 31) ws[w] = v;
    __syncthreads();
    if (t < 8) {
        int x = ws[t];
#pragma unroll
        for (int o = 1; o < 8; o <<= 1) {
            int u = __shfl_up_sync(0xFFu, x, o);
            if (t >= o) x += u;
        }
        ws[t] = x;
    }
    __syncthreads();
    int incl = v + ((w > 0) ? ws[w - 1] : 0);
    int off = poff[blockIdx.x];
    if (i < N) {
        rowptr[i] = off + incl - c;
        dinv[i] = rsqrtf((float)c + 1.f);
        if (i == N - 1) rowptr[N] = off + incl;
    }
}

__global__ void k_fill(const int* __restrict__ ei, const int* __restrict__ rowptr,
                       int* cursor, int* col, int E) {
    int e = blockIdx.x * blockDim.x + threadIdx.x;
    if (e >= E) return;
    int s = ei[e];
    int d = ei[E + e];
    int pos = rowptr[d] + atomicAdd(&cursor[d], 1);
    col[pos] = s;
}

// per-row sort by src (canonical, deterministic) + compute coef values
__global__ void k_rowfin(const int* __restrict__ rowptr, int* __restrict__ col,
                         float* __restrict__ val, const float* __restrict__ dinv, int N) {
    int r = blockIdx.x * blockDim.x + threadIdx.x;
    if (r >= N) return;
    int b = rowptr[r], e = rowptr[r + 1];
    for (int i = b + 1; i < e; i++) {
        int key = col[i];
        int j = i - 1;
        while (j >= b && col[j] > key) { col[j + 1] = col[j]; j--; }
        col[j + 1] = key;
    }
    float dr = dinv[r];
    for (int i = b; i < e; i++) val[i] = dinv[col[i]] * dr;
}

// ---------------- GEMM: H[N,128] = X[N,128] @ W[128,128] ----------------
__global__ void k_gemm(const float* __restrict__ X, const float* __restrict__ W,
                       float* __restrict__ H, int N) {
    __shared__ float Xs[64][33];
    __shared__ float Ws[32][128];
    int t = threadIdx.x;
    int row0 = blockIdx.x * 64;
    int tx = t & 15;
    int ty = t >> 4;

    float acc[4][8];
#pragma unroll
    for (int i = 0; i < 4; i++)
#pragma unroll
        for (int j = 0; j < 8; j++) acc[i][j] = 0.f;

    for (int k0 = 0; k0 < 128; k0 += 32) {
#pragma unroll
        for (int i = t; i < 64 * 32; i += 256) {
            int r = i >> 5, k = i & 31;
            int gr = row0 + r;
            Xs[r][k] = (gr < N) ? X[(size_t)gr * D + k0 + k] : 0.f;
        }
#pragma unroll
        for (int i = t; i < 32 * 128; i += 256) {
            int k = i >> 7, c = i & 127;
            Ws[k][c] = W[(k0 + k) * D + c];
        }
        __syncthreads();
#pragma unroll
        for (int k = 0; k < 32; k++) {
            float a[4], b[8];
#pragma unroll
            for (int i = 0; i < 4; i++) a[i] = Xs[ty * 4 + i][k];
#pragma unroll
            for (int j = 0; j < 8; j++) b[j] = Ws[k][tx + 16 * j];
#pragma unroll
            for (int i = 0; i < 4; i++)
#pragma unroll
                for (int j = 0; j < 8; j++) acc[i][j] = fmaf(a[i], b[j], acc[i][j]);
        }
        __syncthreads();
    }
#pragma unroll
    for (int i = 0; i < 4; i++) {
        int gr = row0 + ty * 4 + i;
        if (gr < N) {
#pragma unroll
            for (int j = 0; j < 8; j++) H[(size_t)gr * D + tx + 16 * j] = acc[i][j];
        }
    }
}

// ---------------- fused aggregation + self-loop + bias + l2norm (+elu) ----------------
__global__ void k_agg(const float* __restrict__ H, const int* __restrict__ rowptr,
                      const int* __restrict__ col, const float* __restrict__ val,
                      const float* __restrict__ dinv, const float* __restrict__ bias,
                      float* __restrict__ X, int N, int elu) {
    int idx = blockIdx.x * blockDim.x + threadIdx.x;
    int row = idx >> 5;
    if (row >= N) return;
    int lane = idx & 31;

    float s = dinv[row]; s *= s;
    float4 h = __ldg(&((const float4*)(H + (size_t)row * D))[lane]);
    float4 b = __ldg(&((const float4*)bias)[lane]);
    float ax = fmaf(h.x, s, b.x);
    float ay = fmaf(h.y, s, b.y);
    float az = fmaf(h.z, s, b.z);
    float aw = fmaf(h.w, s, b.w);

    int beg = rowptr[row], end = rowptr[row + 1];
    int j = beg;
    for (; j + 2 <= end; j += 2) {
        int s0 = col[j], s1 = col[j + 1];
        float c0 = val[j], c1 = val[j + 1];
        float4 v0 = __ldg(&((const float4*)(H + (size_t)s0 * D))[lane]);
        float4 v1 = __ldg(&((const float4*)(H + (size_t)s1 * D))[lane]);
        ax = fmaf(c0, v0.x, ax); ay = fmaf(c0, v0.y, ay);
        az = fmaf(c0, v0.z, az); aw = fmaf(c0, v0.w, aw);
        ax = fmaf(c1, v1.x, ax); ay = fmaf(c1, v1.y, ay);
        az = fmaf(c1, v1.z, az); aw = fmaf(c1, v1.w, aw);
    }
    if (j < end) {
        int s0 = col[j];
        float c0 = val[j];
        float4 v0 = __ldg(&((const float4*)(H + (size_t)s0 * D))[lane]);
        ax = fmaf(c0, v0.x, ax); ay = fmaf(c0, v0.y, ay);
        az = fmaf(c0, v0.z, az); aw = fmaf(c0, v0.w, aw);
    }

    float ss = ax * ax + ay * ay + az * az + aw * aw;
#pragma unroll
    for (int o = 16; o > 0; o >>= 1) ss += __shfl_xor_sync(0xFFFFFFFFu, ss, o);
    float inv = 1.f / fmaxf(sqrtf(ss), 1e-12f);
    ax *= inv; ay *= inv; az *= inv; aw *= inv;
    if (elu) {
        ax = ax > 0.f ? ax : expm1f(ax);
        ay = ay > 0.f ? ay : expm1f(ay);
        az = az > 0.f ? az : expm1f(az);
        aw = aw > 0.f ? aw : expm1f(aw);
    }
    ((float4*)(X + (size_t)row * D))[lane] = make_float4(ax, ay, az, aw);
}

// ---------------- consensus ----------------
__global__ void k_cons(const float* __restrict__ Xq, float* __restrict__ Xt,
                       const int* __restrict__ umap, const int* __restrict__ vmap) {
    int idx = blockIdx.x * blockDim.x + threadIdx.x;
    int row = idx >> 5, lane = idx & 31;
    if (row >= NMAP) return;
    int us = umap[row], vd = vmap[row];
    ((float4*)(Xt + (size_t)vd * D))[lane] = ((const float4*)(Xq + (size_t)us * D))[lane];
}

// ---------------- bilinear stage A ----------------
__global__ void k_bilinA(const float* __restrict__ Xq, const int* __restrict__ u_ptr,
                         const float* __restrict__ Wb, float* __restrict__ T) {
    __shared__ float a[D];
    int o = blockIdx.x;
    int k = threadIdx.x;
    int u = *u_ptr;
    a[k] = Xq[(size_t)u * D + k];
    __syncthreads();
    const float* w = Wb + (size_t)o * D * D + k;
    float acc = 0.f;
#pragma unroll 8
    for (int j = 0; j < D; j++) acc = fmaf(a[j], w[(size_t)j * D], acc);
    T[o * D + k] = acc;
}

// ---------------- bilinear stage B ----------------
__global__ void k_bilinB(const float* __restrict__ T, const float* __restrict__ Xt,
                         const int* __restrict__ v_li, const float* __restrict__ bb,
                         float* __restrict__ feat, int col0) {
    __shared__ float x[D];
    int v = blockIdx.x;
    int t = threadIdx.x;
    int vv = v_li[v];
    x[t] = Xt[(size_t)vv * D + t];
    x[t + 64] = Xt[(size_t)vv * D + 64 + t];
    __syncthreads();
    const float* tr = T + t * D;
    float acc = bb[t];
#pragma unroll 8
    for (int k = 0; k < D; k++) acc = fmaf(tr[k], x[k], acc);
    feat[v * DMLP + col0 + t] = acc;
}

// ---------------- MLP head ----------------
__global__ void k_mlp(const float* __restrict__ feat,
                      const float* __restrict__ W1, const float* __restrict__ b1,
                      const float* __restrict__ W2, const float* __restrict__ b2,
                      const float* __restrict__ W3, const float* __restrict__ b3,
                      float* __restrict__ out) {
    __shared__ float f[DMLP];
    __shared__ float h1[96];
    __shared__ float h2[48];
    int v = blockIdx.x;
    int t = threadIdx.x;
    f[t] = feat[v * DMLP + t];
    f[t + 96] = feat[v * DMLP + 96 + t];
    __syncthreads();
    float acc = b1[t];
#pragma unroll 8
    for (int j = 0; j < DMLP; j++) acc = fmaf(f[j], W1[j * 96 + t], acc);
    h1[t] = fmaxf(acc, 0.f);
    __syncthreads();
    if (t < 48) {
        float a2 = b2[t];
#pragma unroll 8
        for (int j = 0; j < 96; j++) a2 = fmaf(h1[j], W2[j * 48 + t], a2);
        h2[t] = fmaxf(a2, 0.f);
    }
    __syncthreads();
    if (t == 0) {
        float s = b3[0];
#pragma unroll
        for (int j = 0; j < 48; j++) s = fmaf(h2[j], W3[j], s);
        out[v] = s;
    }
}

// ---------------- launch ----------------
extern "C" void kernel_launch(void* const* d_in, const int* in_sizes, int n_in,
                              void* d_out, int out_size) {
    const float* x_q  = (const float*)d_in[0];
    const float* x_t  = (const float*)d_in[1];
    const int*   eiq  = (const int*)d_in[2];
    const int*   eit  = (const int*)d_in[3];
    const int*   u    = (const int*)d_in[4];
    const int*   v_li = (const int*)d_in[5];
    const int*   umap = (const int*)d_in[6];
    const int*   vmap = (const int*)d_in[7];
    const float* Wg   = (const float*)d_in[8];
    const float* bg   = (const float*)d_in[9];
    const float* Wb   = (const float*)d_in[10];
    const float* bb   = (const float*)d_in[11];
    const float* W1   = (const float*)d_in[12];
    const float* b1   = (const float*)d_in[13];
    const float* W2   = (const float*)d_in[14];
    const float* b2   = (const float*)d_in[15];
    const float* W3   = (const float*)d_in[16];
    const float* b3   = (const float*)d_in[17];

    float* out = (float*)d_out;
    float* Xq  = out + KVN;
    float* Xt  = Xq + (size_t)NQN * D;

    float *Hq, *Ht, *dq, *dt, *vq, *vt, *T, *feat;
    int *cq, *ct, *rq, *rt, *colq, *colt, *pq, *pt;
    cudaGetSymbolAddress((void**)&Hq, g_Hq);
    cudaGetSymbolAddress((void**)&Ht, g_Ht);
    cudaGetSymbolAddress((void**)&dq, g_dinvq);
    cudaGetSymbolAddress((void**)&dt, g_dinvt);
    cudaGetSymbolAddress((void**)&cq, g_cntq);
    cudaGetSymbolAddress((void**)&ct, g_cntt);
    cudaGetSymbolAddress((void**)&rq, g_rowq);
    cudaGetSymbolAddress((void**)&rt, g_rowt);
    cudaGetSymbolAddress((void**)&colq, g_colq);
    cudaGetSymbolAddress((void**)&colt, g_colt);
    cudaGetSymbolAddress((void**)&vq, g_valq);
    cudaGetSymbolAddress((void**)&vt, g_valt);
    cudaGetSymbolAddress((void**)&pq, g_partq);
    cudaGetSymbolAddress((void**)&pt, g_partt);
    cudaGetSymbolAddress((void**)&T, g_T);
    cudaGetSymbolAddress((void**)&feat, g_feat);

    const int TB = 256;
    const int NBQ = (NQN + 255) / 256;   // 4
    const int NBT = (NTN + 255) / 256;   // 391

    // ---- CSR build (graph-static, once per launch) ----
    k_zeroi<<<(NQN + TB - 1) / TB, TB>>>(cq, NQN);
    k_zeroi<<<(NTN + TB - 1) / TB, TB>>>(ct, NTN);
    k_hist<<<(EQN + TB - 1) / TB, TB>>>(eiq + EQN, cq, EQN);
    k_hist<<<(ETN + TB - 1) / TB, TB>>>(eit + ETN, ct, ETN);
    k_partial<<<NBQ, 256>>>(cq, pq, NQN);
    k_partial<<<NBT, 256>>>(ct, pt, NTN);
    k_scanp<<<1, 512>>>(pq, NBQ);
    k_scanp<<<1, 512>>>(pt, NBT);
    k_rowptr<<<NBQ, 256>>>(cq, pq, rq, dq, NQN);
    k_rowptr<<<NBT, 256>>>(ct, pt, rt, dt, NTN);
    k_zeroi<<<(NQN + TB - 1) / TB, TB>>>(cq, NQN);
    k_zeroi<<<(NTN + TB - 1) / TB, TB>>>(ct, NTN);
    k_fill<<<(EQN + TB - 1) / TB, TB>>>(eiq, rq, cq, colq, EQN);
    k_fill<<<(ETN + TB - 1) / TB, TB>>>(eit, rt, ct, colt, ETN);
    k_rowfin<<<(NQN + TB - 1) / TB, TB>>>(rq, colq, vq, dq, NQN);
    k_rowfin<<<(NTN + TB - 1) / TB, TB>>>(rt, colt, vt, dt, NTN);

    for (int i = 0; i < 3; i++) {
        const float* Wi = Wg + (size_t)i * D * D;
        const float* bi = bg + (size_t)i * D;
        const float* Xq_in = (i == 0) ? x_q : Xq;
        const float* Xt_in = (i == 0) ? x_t : Xt;
        int elu = (i < 2) ? 1 : 0;

        k_gemm<<<(NQN + 63) / 64, TB>>>(Xq_in, Wi, Hq, NQN);
        k_gemm<<<(NTN + 63) / 64, TB>>>(Xt_in, Wi, Ht, NTN);

        k_agg<<<((NQN * 32) + TB - 1) / TB, TB>>>(Hq, rq, colq, vq, dq, bi, Xq, NQN, elu);
        k_agg<<<((size_t)(NTN) * 32 + TB - 1) / TB, TB>>>(Ht, rt, colt, vt, dt, bi, Xt, NTN, elu);

        k_cons<<<(NMAP * 32 + TB - 1) / TB, TB>>>(Xq, Xt, umap, vmap);

        k_bilinA<<<DBIL, D>>>(Xq, u, Wb + (size_t)i * DBIL * D * D, T);
        k_bilinB<<<KVN, DBIL>>>(T, Xt, v_li, bb + (size_t)i * DBIL, feat, i * DBIL);
    }

    k_mlp<<<KVN, 96>>>(feat, W1, b1, W2, b2, W3, b3, out);
}